// round 15
// baseline (speedup 1.0000x reference)
#include <cuda_runtime.h>
#include <cuda_fp16.h>
#include <cstdint>

#define N_NODES 100000
#define N_EDGES 1600000
#define IN_CH   512
#define HID_CH  256
#define OUT_CH  64
#define K_STEPS 10
#define NB_SCAN ((N_NODES + 255) / 256)   // 391
#define W1_ELEMS (IN_CH * HID_CH)
#define W2_ELEMS (HID_CH * OUT_CH)

// ---------------- scratch (static __device__, no allocation) ----------------
__device__ int   g_deg[N_NODES];
__device__ int   g_cursor[N_NODES];
__device__ float g_dinv[N_NODES];
__device__ float g_selfw[N_NODES];
__device__ int   g_rowptr[N_NODES + 1];
__device__ int   g_part[NB_SCAN];
__device__ __align__(16) int2   g_epack[N_EDGES];
__device__ __align__(16) __half g_w1h[W1_ELEMS];   // w1 [K][N] fp16
__device__ __align__(16) __half g_w2h[W2_ELEMS];   // w2 [K][N] fp16
__device__ __align__(16) __half g_hidh[(size_t)N_NODES * HID_CH];  // fp16 hidden
__device__ __align__(16) __half g_h0h [(size_t)N_NODES * OUT_CH];  // fp16 h0
__device__ __align__(16) __half g_ha  [(size_t)N_NODES * OUT_CH];
__device__ __align__(16) __half g_hb  [(size_t)N_NODES * OUT_CH];

// ---------------- preprocessing ----------------
__global__ void init_and_convert(const float* __restrict__ w1,
                                 const float* __restrict__ w2)
{
    int i = blockIdx.x * blockDim.x + threadIdx.x;
    if (i < N_NODES) { g_deg[i] = 1; g_cursor[i] = 0; }
    if (i < W1_ELEMS) g_w1h[i] = __float2half_rn(w1[i]);
    if (i < W2_ELEMS) g_w2h[i] = __float2half_rn(w2[i]);
}

__global__ void count_deg(const int* __restrict__ ei)
{
    int e = blockIdx.x * blockDim.x + threadIdx.x;
    if (e < N_EDGES) {
        int d = ei[N_EDGES + e];
        if ((unsigned)d < N_NODES) atomicAdd(&g_deg[d], 1);
    }
}

__global__ void compute_dinv()
{
    int i = blockIdx.x * blockDim.x + threadIdx.x;
    if (i < N_NODES) {
        float dv = rsqrtf((float)g_deg[i]);
        g_dinv[i]  = dv;
        g_selfw[i] = 0.9f * dv * dv;
    }
}

__global__ void scan_p1()
{
    int b = blockIdx.x, t = threadIdx.x;
    int i = b * 256 + t;
    int v = (i < N_NODES) ? (g_deg[i] - 1) : 0;
    int lane = t & 31, w = t >> 5;
    int x = v;
    #pragma unroll
    for (int o = 1; o < 32; o <<= 1) {
        int y = __shfl_up_sync(0xffffffffu, x, o);
        if (lane >= o) x += y;
    }
    __shared__ int wsum[8];
    if (lane == 31) wsum[w] = x;
    __syncthreads();
    if (t < 8) {
        int s = wsum[t];
        #pragma unroll
        for (int o = 1; o < 8; o <<= 1) {
            int y = __shfl_up_sync(0xffu, s, o);
            if (t >= o) s += y;
        }
        wsum[t] = s;
    }
    __syncthreads();
    int base = (w > 0) ? wsum[w - 1] : 0;
    if (i < N_NODES) g_rowptr[i] = base + x - v;
    if (t == 255) g_part[b] = wsum[7];
}

__global__ void scan_p2()
{
    __shared__ int s[512];
    int t = threadIdx.x;
    int v = (t < NB_SCAN) ? g_part[t] : 0;
    s[t] = v;
    __syncthreads();
    for (int o = 1; o < 512; o <<= 1) {
        int y = (t >= o) ? s[t - o] : 0;
        __syncthreads();
        s[t] += y;
        __syncthreads();
    }
    if (t < NB_SCAN) g_part[t] = s[t] - v;
    if (t == NB_SCAN - 1) g_rowptr[N_NODES] = s[t];
}

__global__ void scan_p3()
{
    int b = blockIdx.x, t = threadIdx.x;
    int i = b * 256 + t;
    if (i < N_NODES) g_rowptr[i] += g_part[b];
}

__global__ void fill_csr(const int* __restrict__ ei)
{
    int idx = blockIdx.x * blockDim.x + threadIdx.x;
    if (idx < N_EDGES) {
        int s = ei[idx];
        int d = ei[N_EDGES + idx];
        if ((unsigned)s >= N_NODES || (unsigned)d >= N_NODES) return;
        int pos = g_rowptr[d] + atomicAdd(&g_cursor[d], 1);
        int2 p;
        p.x = s;
        p.y = __float_as_int(0.9f * g_dinv[s] * g_dinv[d]);
        g_epack[pos] = p;
    }
}

// ---------------- fp16 tensor-core GEMM: cp.async + ldmatrix, BK=32 ----------------
__device__ __forceinline__ void cp_async16s(unsigned smem_addr, const void* gmem_src, bool valid)
{
    int sz = valid ? 16 : 0;
    asm volatile("cp.async.cg.shared.global [%0], [%1], 16, %2;\n"
                 :: "r"(smem_addr), "l"(gmem_src), "r"(sz));
}
#define CP_COMMIT() asm volatile("cp.async.commit_group;\n" ::: "memory")
#define CP_WAIT(n)  asm volatile("cp.async.wait_group %0;\n" :: "n"(n) : "memory")

#define MMA_F16(d, a, b)                                                          \
    asm volatile("mma.sync.aligned.m16n8k16.row.col.f32.f16.f16.f32 "             \
                 "{%0,%1,%2,%3},{%4,%5,%6,%7},{%8,%9},{%0,%1,%2,%3};\n"           \
                 : "+f"(d[0]), "+f"(d[1]), "+f"(d[2]), "+f"(d[3])                 \
                 : "r"(a[0]), "r"(a[1]), "r"(a[2]), "r"(a[3]),                    \
                   "r"(b[0]), "r"(b[1]))

#define LDMX4(r0, r1, r2, r3, addr)                                               \
    asm volatile("ldmatrix.sync.aligned.m8n8.x4.shared.b16 {%0,%1,%2,%3}, [%4];"  \
                 : "=r"(r0), "=r"(r1), "=r"(r2), "=r"(r3) : "r"(addr))

#define LDMX4T(r0, r1, r2, r3, addr)                                                   \
    asm volatile("ldmatrix.sync.aligned.m8n8.x4.trans.shared.b16 {%0,%1,%2,%3}, [%4];" \
                 : "=r"(r0), "=r"(r1), "=r"(r2), "=r"(r3) : "r"(addr))

__device__ __forceinline__ unsigned packh2(float lo, float hi)
{
    __half2 h = __floats2half2_rn(lo, hi);
    return *(unsigned*)&h;
}

// BM=128, BK=32, 512 threads (16 warps as 4m x 4n -> warp tile 32 x BN/4).
// fp16 m16n8k16 MMA, fp32 accumulate. 2 CTAs/SM.
// AF32: A fp32 in gmem, staged through regs (LDG.128 x2 -> pack -> STS.128)
//       with distance-1 prefetch into a 2-stage fp16 smem buffer.
// else: A fp16 in gmem via 3-stage cp.async.
// B fp16 [K][N] via 3-stage cp.async. Fragments via ldmatrix.
template<int BN, bool AF32, bool RELU, bool OUTF, bool OUTH>
__global__ __launch_bounds__(512, 2) void gemm_kernel(
    const void* __restrict__ Av, const __half* __restrict__ B,
    const float* __restrict__ bias, float* __restrict__ C,
    __half* __restrict__ Ch, int M, int N, int Kd)
{
    const int BM = 128, BK = 32;
    const int ASTG = AF32 ? 2 : 3;           // A smem stages
    const int NT = BN / 32;                  // n-frags per warp (4 or 2)
    const int A_STRIDE = 80;                 // 32 halves (64B) + 16B pad
    const int A_BYTES  = BM * A_STRIDE;      // 10240
    const int B_STRIDE = BN * 2 + 16;
    const int B_BYTES  = BK * B_STRIDE;

    __shared__ __align__(16) char sm[ASTG * A_BYTES + 3 * B_BYTES];
    unsigned smS = (unsigned)__cvta_generic_to_shared(sm);
    unsigned AbS = smS;
    unsigned BbS = smS + ASTG * A_BYTES;

    int tid  = threadIdx.x;
    int warp = tid >> 5, lane = tid & 31;
    int wm = warp >> 2;
    int wn = warp & 3;
    int bm0 = blockIdx.y * BM;
    int bn0 = blockIdx.x * BN;

    float acc[2][NT][4];
    #pragma unroll
    for (int i = 0; i < 2; i++)
        #pragma unroll
        for (int j = 0; j < NT; j++)
            #pragma unroll
            for (int l = 0; l < 4; l++) acc[i][j][l] = 0.0f;

    int g = lane >> 3, lr = lane & 7;
    unsigned a_base = (unsigned)((wm * 32 + (g & 1) * 8 + lr) * A_STRIDE + (g >> 1) * 16);

    // staging coords
    int arow = tid >> 2, ac = tid & 3;       // 128 rows x 4 chunks (16B fp16 / 32B fp32)
    int agr = bm0 + arow;
    int acl = (agr < M) ? agr : (M - 1);     // clamp: garbage rows masked at epilogue

    float4 ra0, ra1;                          // AF32 reg staging
    auto ldgA = [&](int k0) {
        const float4* p = (const float4*)((const float*)Av + (size_t)acl * Kd + k0 + ac * 8);
        ra0 = __ldg(p);
        ra1 = __ldg(p + 1);
    };
    auto stsA = [&](int buf) {
        unsigned o0 = packh2(ra0.x, ra0.y), o1 = packh2(ra0.z, ra0.w);
        unsigned o2 = packh2(ra1.x, ra1.y), o3 = packh2(ra1.z, ra1.w);
        asm volatile("st.shared.v4.b32 [%0], {%1,%2,%3,%4};"
                     :: "r"(AbS + buf * A_BYTES + arow * A_STRIDE + ac * 16),
                        "r"(o0), "r"(o1), "r"(o2), "r"(o3));
    };
    auto cpA = [&](int buf, int k0) {
        cp_async16s(AbS + buf * A_BYTES + arow * A_STRIDE + ac * 16,
                    (const __half*)Av + (size_t)acl * Kd + k0 + ac * 8, agr < M);
    };
    auto cpB = [&](int buf, int k0) {
        if (tid < BK * (BN / 8)) {
            int br = tid / (BN / 8), bc = tid % (BN / 8);
            cp_async16s(BbS + buf * B_BYTES + br * B_STRIDE + bc * 16,
                        B + (size_t)(k0 + br) * N + bn0 + bc * 8, true);
        }
    };

    int nIter = Kd / BK;
    if (AF32) {
        ldgA(0);
        cpB(0, 0);           CP_COMMIT();
        if (1 < nIter) cpB(1, BK);
        CP_COMMIT();
    } else {
        cpA(0, 0); cpB(0, 0);           CP_COMMIT();
        if (1 < nIter) { cpA(1, BK); cpB(1, BK); }
        CP_COMMIT();
    }

    for (int it = 0; it < nIter; it++) {
        int curA = AF32 ? (it & 1) : (it % 3);
        int curB = it % 3;

        if (AF32) stsA(curA);
        CP_WAIT(1);
        __syncthreads();

        if (AF32) {
            if (it + 1 < nIter) ldgA((it + 1) * BK);
            if (it + 2 < nIter) cpB((it + 2) % 3, (it + 2) * BK);
            CP_COMMIT();
        } else {
            if (it + 2 < nIter) {
                cpA((it + 2) % 3, (it + 2) * BK);
                cpB((it + 2) % 3, (it + 2) * BK);
            }
            CP_COMMIT();
        }

        unsigned Ab = AbS + curA * A_BYTES;
        unsigned Bb = BbS + curB * B_BYTES;

        #pragma unroll
        for (int kc = 0; kc < 2; kc++) {
            unsigned a0[4], a1[4], b[NT][2];
            LDMX4(a0[0], a0[1], a0[2], a0[3], Ab + a_base + kc * 32);
            LDMX4(a1[0], a1[1], a1[2], a1[3], Ab + a_base + 16 * A_STRIDE + kc * 32);
            if (BN == 128) {
                unsigned bo = Bb + (kc * 16 + lr) * B_STRIDE + (wn * 32 + g * 8) * 2;
                LDMX4T(b[0][0], b[1][0], b[2][0], b[3][0], bo);
                LDMX4T(b[0][1], b[1][1], b[2][1], b[3][1], bo + 8 * B_STRIDE);
            } else {
                unsigned bo = Bb + (kc * 16 + (g >> 1) * 8 + lr) * B_STRIDE
                            + (wn * 16 + (g & 1) * 8) * 2;
                LDMX4T(b[0][0], b[1][0], b[0][1], b[1][1], bo);
            }
            #pragma unroll
            for (int nt = 0; nt < NT; nt++) {
                MMA_F16(acc[0][nt], a0, b[nt]);
                MMA_F16(acc[1][nt], a1, b[nt]);
            }
        }
    }

    #pragma unroll
    for (int mt = 0; mt < 2; mt++) {
        #pragma unroll
        for (int nt = 0; nt < NT; nt++) {
            int r0 = bm0 + wm * 32 + mt * 16 + (lane >> 2);
            int c0 = bn0 + wn * (BN / 4) + nt * 8 + (lane & 3) * 2;
            float bv0 = bias[c0], bv1 = bias[c0 + 1];
            #pragma unroll
            for (int h = 0; h < 2; h++) {
                int r = r0 + h * 8;
                if (r < M) {
                    float v0 = acc[mt][nt][h * 2 + 0] + bv0;
                    float v1 = acc[mt][nt][h * 2 + 1] + bv1;
                    if (RELU) { v0 = fmaxf(v0, 0.f); v1 = fmaxf(v1, 0.f); }
                    if (OUTF) {
                        C[(size_t)r * N + c0]     = v0;
                        C[(size_t)r * N + c0 + 1] = v1;
                    }
                    if (OUTH) {
                        *(__half2*)&Ch[(size_t)r * N + c0] = __floats2half2_rn(v0, v1);
                    }
                }
            }
        }
    }
}

// ---------------- propagation (fp16 storage, fp32 accumulation) ----------------
template<bool OUT_HALF>
__global__ __launch_bounds__(256) void prop_kernel(
    const __half* __restrict__ hin, void* __restrict__ hout,
    const __half* __restrict__ h0)
{
    int gt = blockIdx.x * blockDim.x + threadIdx.x;
    int v = gt >> 4;
    if (v >= N_NODES) return;
    int lane = gt & 15;

    int e0 = g_rowptr[v];
    int e1 = g_rowptr[v + 1];
    const uint2* h2 = (const uint2*)hin;

    float4 acc = make_float4(0.f, 0.f, 0.f, 0.f);
    auto accum = [&](float w, uint2 hv) {
        float2 lo = __half22float2(*(const __half2*)&hv.x);
        float2 hi = __half22float2(*(const __half2*)&hv.y);
        acc.x = fmaf(w, lo.x, acc.x); acc.y = fmaf(w, lo.y, acc.y);
        acc.z = fmaf(w, hi.x, acc.z); acc.w = fmaf(w, hi.y, acc.w);
    };

    int e = e0;
    if ((e & 1) && e < e1) {                  // align to 16B pair boundary
        int2 p = __ldg(&g_epack[e]);
        accum(__int_as_float(p.y), h2[(size_t)p.x * 16 + lane]);
        e++;
    }
    for (; e + 4 <= e1; e += 4) {             // 4 independent gathers in flight
        int4 p01 = __ldg((const int4*)&g_epack[e]);
        int4 p23 = __ldg((const int4*)&g_epack[e + 2]);
        uint2 hv0 = h2[(size_t)p01.x * 16 + lane];
        uint2 hv1 = h2[(size_t)p01.z * 16 + lane];
        uint2 hv2 = h2[(size_t)p23.x * 16 + lane];
        uint2 hv3 = h2[(size_t)p23.z * 16 + lane];
        accum(__int_as_float(p01.y), hv0);
        accum(__int_as_float(p01.w), hv1);
        accum(__int_as_float(p23.y), hv2);
        accum(__int_as_float(p23.w), hv3);
    }
    if (e + 2 <= e1) {
        int4 p = __ldg((const int4*)&g_epack[e]);
        uint2 hv0 = h2[(size_t)p.x * 16 + lane];
        uint2 hv1 = h2[(size_t)p.z * 16 + lane];
        accum(__int_as_float(p.y), hv0);
        accum(__int_as_float(p.w), hv1);
        e += 2;
    }
    if (e < e1) {
        int2 p = __ldg(&g_epack[e]);
        accum(__int_as_float(p.y), h2[(size_t)p.x * 16 + lane]);
    }

    accum(g_selfw[v], h2[(size_t)v * 16 + lane]);

    uint2 z2 = ((const uint2*)h0)[(size_t)v * 16 + lane];
    float2 zlo = __half22float2(*(const __half2*)&z2.x);
    float2 zhi = __half22float2(*(const __half2*)&z2.y);
    float4 r;
    r.x = acc.x + 0.1f * zlo.x;
    r.y = acc.y + 0.1f * zlo.y;
    r.z = acc.z + 0.1f * zhi.x;
    r.w = acc.w + 0.1f * zhi.y;

    if (OUT_HALF) {
        uint2 o;
        *(__half2*)&o.x = __floats2half2_rn(r.x, r.y);
        *(__half2*)&o.y = __floats2half2_rn(r.z, r.w);
        ((uint2*)hout)[(size_t)v * 16 + lane] = o;
    } else {
        ((float4*)hout)[(size_t)v * 16 + lane] = r;
    }
}

// ---------------- launch ----------------
extern "C" void kernel_launch(void* const* d_in, const int* in_sizes, int n_in,
                              void* d_out, int out_size)
{
    const float* x  = (const float*)d_in[0];
    const int*   ei = (const int*)d_in[1];     // int32 [2, E]
    const float* w1 = (const float*)d_in[2];
    const float* b1 = (const float*)d_in[3];
    const float* w2 = (const float*)d_in[4];
    const float* b2 = (const float*)d_in[5];
    float*       out = (float*)d_out;

    __half *p_w1h, *p_w2h, *p_hidh, *p_h0h, *p_ha, *p_hb;
    cudaGetSymbolAddress((void**)&p_w1h,  g_w1h);
    cudaGetSymbolAddress((void**)&p_w2h,  g_w2h);
    cudaGetSymbolAddress((void**)&p_hidh, g_hidh);
    cudaGetSymbolAddress((void**)&p_h0h,  g_h0h);
    cudaGetSymbolAddress((void**)&p_ha,   g_ha);
    cudaGetSymbolAddress((void**)&p_hb,   g_hb);

    // launches 0-2: preprocessing (weights fp16 fused into 0; x stays fp32)
    init_and_convert<<<(W1_ELEMS + 255) / 256, 256>>>(w1, w2);
    count_deg<<<(N_EDGES + 255) / 256, 256>>>(ei);
    compute_dinv<<<(N_NODES + 255) / 256, 256>>>();

    // launch index 3 (ncu slot): GEMM1 — fp32 A (x) converted in-kernel, fp16 B
    dim3 g1(HID_CH / 128, (N_NODES + 127) / 128);
    gemm_kernel<128, true, true, false, true><<<g1, 512>>>(
        x, p_w1h, b1, nullptr, p_hidh, N_NODES, HID_CH, IN_CH);

    scan_p1<<<NB_SCAN, 256>>>();
    scan_p2<<<1, 512>>>();
    scan_p3<<<NB_SCAN, 256>>>();
    fill_csr<<<(N_EDGES + 255) / 256, 256>>>(ei);

    // GEMM2 — fp16 A (hidden) via cp.async, fp16 B; writes fp16 h0
    dim3 g2(1, (N_NODES + 127) / 128);
    gemm_kernel<64, false, false, false, true><<<g2, 512>>>(
        p_hidh, p_w2h, b2, nullptr, p_h0h, N_NODES, OUT_CH, HID_CH);

    // APPNP: steps 0..8 fp16 ping-pong, step 9 writes fp32 to d_out
    int grid = (N_NODES * 16 + 255) / 256;
    const __half* cur = p_h0h;
    for (int s = 0; s < K_STEPS - 1; s++) {
        __half* o = (s & 1) ? p_hb : p_ha;
        prop_kernel<true><<<grid, 256>>>(cur, o, p_h0h);
        cur = o;
    }
    prop_kernel<false><<<grid, 256>>>(cur, out, p_h0h);
}

// round 16
// speedup vs baseline: 1.0567x; 1.0567x over previous
#include <cuda_runtime.h>
#include <cuda_fp16.h>
#include <cstdint>

#define N_NODES 100000
#define N_EDGES 1600000
#define IN_CH   512
#define HID_CH  256
#define OUT_CH  64
#define K_STEPS 10
#define NB_SCAN ((N_NODES + 255) / 256)   // 391
#define W1_ELEMS (IN_CH * HID_CH)
#define W2_ELEMS (HID_CH * OUT_CH)
#define X_ELEMS  (N_NODES * IN_CH)         // 51.2M

// ---------------- scratch (static __device__, no allocation) ----------------
__device__ int   g_deg[N_NODES];
__device__ int   g_cursor[N_NODES];
__device__ float g_dinv[N_NODES];
__device__ float g_selfw[N_NODES];
__device__ int   g_rowptr[N_NODES + 1];
__device__ int   g_part[NB_SCAN];
__device__ __align__(16) int2   g_epack[N_EDGES];
__device__ __align__(16) __half g_xh [(size_t)X_ELEMS];            // fp16 x
__device__ __align__(16) __half g_w1h[W1_ELEMS];   // w1 [K][N] fp16
__device__ __align__(16) __half g_w2h[W2_ELEMS];   // w2 [K][N] fp16
__device__ __align__(16) __half g_hidh[(size_t)N_NODES * HID_CH];  // fp16 hidden
__device__ __align__(16) __half g_h0h [(size_t)N_NODES * OUT_CH];  // fp16 h0
__device__ __align__(16) __half g_ha  [(size_t)N_NODES * OUT_CH];
__device__ __align__(16) __half g_hb  [(size_t)N_NODES * OUT_CH];

// ---------------- preprocessing ----------------
__global__ void init_and_convert(const float4* __restrict__ x4,
                                 const float* __restrict__ w1,
                                 const float* __restrict__ w2)
{
    int i = blockIdx.x * blockDim.x + threadIdx.x;
    if (i < X_ELEMS / 4) {
        float4 v = x4[i];
        uint2 o;
        *(__half2*)&o.x = __floats2half2_rn(v.x, v.y);
        *(__half2*)&o.y = __floats2half2_rn(v.z, v.w);
        ((uint2*)g_xh)[i] = o;
    }
    if (i < N_NODES) { g_deg[i] = 1; g_cursor[i] = 0; }
    if (i < W1_ELEMS) g_w1h[i] = __float2half_rn(w1[i]);
    if (i < W2_ELEMS) g_w2h[i] = __float2half_rn(w2[i]);
}

__global__ void count_deg(const int* __restrict__ ei)
{
    int e = blockIdx.x * blockDim.x + threadIdx.x;
    if (e < N_EDGES) {
        int d = ei[N_EDGES + e];
        if ((unsigned)d < N_NODES) atomicAdd(&g_deg[d], 1);
    }
}

__global__ void compute_dinv()
{
    int i = blockIdx.x * blockDim.x + threadIdx.x;
    if (i < N_NODES) {
        float dv = rsqrtf((float)g_deg[i]);
        g_dinv[i]  = dv;
        g_selfw[i] = 0.9f * dv * dv;
    }
}

__global__ void scan_p1()
{
    int b = blockIdx.x, t = threadIdx.x;
    int i = b * 256 + t;
    int v = (i < N_NODES) ? (g_deg[i] - 1) : 0;
    int lane = t & 31, w = t >> 5;
    int x = v;
    #pragma unroll
    for (int o = 1; o < 32; o <<= 1) {
        int y = __shfl_up_sync(0xffffffffu, x, o);
        if (lane >= o) x += y;
    }
    __shared__ int wsum[8];
    if (lane == 31) wsum[w] = x;
    __syncthreads();
    if (t < 8) {
        int s = wsum[t];
        #pragma unroll
        for (int o = 1; o < 8; o <<= 1) {
            int y = __shfl_up_sync(0xffu, s, o);
            if (t >= o) s += y;
        }
        wsum[t] = s;
    }
    __syncthreads();
    int base = (w > 0) ? wsum[w - 1] : 0;
    if (i < N_NODES) g_rowptr[i] = base + x - v;
    if (t == 255) g_part[b] = wsum[7];
}

__global__ void scan_p2()
{
    __shared__ int s[512];
    int t = threadIdx.x;
    int v = (t < NB_SCAN) ? g_part[t] : 0;
    s[t] = v;
    __syncthreads();
    for (int o = 1; o < 512; o <<= 1) {
        int y = (t >= o) ? s[t - o] : 0;
        __syncthreads();
        s[t] += y;
        __syncthreads();
    }
    if (t < NB_SCAN) g_part[t] = s[t] - v;
    if (t == NB_SCAN - 1) g_rowptr[N_NODES] = s[t];
}

__global__ void scan_p3()
{
    int b = blockIdx.x, t = threadIdx.x;
    int i = b * 256 + t;
    if (i < N_NODES) g_rowptr[i] += g_part[b];
}

__global__ void fill_csr(const int* __restrict__ ei)
{
    int idx = blockIdx.x * blockDim.x + threadIdx.x;
    if (idx < N_EDGES) {
        int s = ei[idx];
        int d = ei[N_EDGES + idx];
        if ((unsigned)s >= N_NODES || (unsigned)d >= N_NODES) return;
        int pos = g_rowptr[d] + atomicAdd(&g_cursor[d], 1);
        int2 p;
        p.x = s;
        p.y = __float_as_int(0.9f * g_dinv[s] * g_dinv[d]);
        g_epack[pos] = p;
    }
}

// ---------------- fp16 tensor-core GEMM: cp.async + ldmatrix, BK=32 ----------------
__device__ __forceinline__ void cp_async16s(unsigned smem_addr, const void* gmem_src, bool valid)
{
    int sz = valid ? 16 : 0;
    asm volatile("cp.async.cg.shared.global [%0], [%1], 16, %2;\n"
                 :: "r"(smem_addr), "l"(gmem_src), "r"(sz));
}
#define CP_COMMIT() asm volatile("cp.async.commit_group;\n" ::: "memory")
#define CP_WAIT(n)  asm volatile("cp.async.wait_group %0;\n" :: "n"(n) : "memory")

#define MMA_F16(d, a, b)                                                          \
    asm volatile("mma.sync.aligned.m16n8k16.row.col.f32.f16.f16.f32 "             \
                 "{%0,%1,%2,%3},{%4,%5,%6,%7},{%8,%9},{%0,%1,%2,%3};\n"           \
                 : "+f"(d[0]), "+f"(d[1]), "+f"(d[2]), "+f"(d[3])                 \
                 : "r"(a[0]), "r"(a[1]), "r"(a[2]), "r"(a[3]),                    \
                   "r"(b[0]), "r"(b[1]))

#define LDMX4(r0, r1, r2, r3, addr)                                               \
    asm volatile("ldmatrix.sync.aligned.m8n8.x4.shared.b16 {%0,%1,%2,%3}, [%4];"  \
                 : "=r"(r0), "=r"(r1), "=r"(r2), "=r"(r3) : "r"(addr))

#define LDMX4T(r0, r1, r2, r3, addr)                                                   \
    asm volatile("ldmatrix.sync.aligned.m8n8.x4.trans.shared.b16 {%0,%1,%2,%3}, [%4];" \
                 : "=r"(r0), "=r"(r1), "=r"(r2), "=r"(r3) : "r"(addr))

// BM=128, BK=32, 512 threads (16 warps as 4m x 4n -> warp tile 32 x BN/4).
// 3-stage cp.async pipeline (dynamic smem), 2 CTAs/SM. fp16 m16n8k16, fp32 acc.
// A fp16 [M][K]; B fp16 [K][N]. Fragments via ldmatrix. One sync per 16 MMAs.
template<int BN, bool RELU, bool OUTF, bool OUTH>
__global__ __launch_bounds__(512, 2) void gemm_kernel(
    const __half* __restrict__ A, const __half* __restrict__ B,
    const float* __restrict__ bias, float* __restrict__ C,
    __half* __restrict__ Ch, int M, int N, int Kd)
{
    const int BM = 128, BK = 32, STAGES = 3;
    const int NT = BN / 32;                  // n-frags per warp (4 or 2)
    const int A_STRIDE = 80;                 // 32 halves (64B) + 16B pad
    const int A_BYTES  = BM * A_STRIDE;      // 10240
    const int B_STRIDE = BN * 2 + 16;        // row of BN halves + 16B pad
    const int B_BYTES  = BK * B_STRIDE;

    extern __shared__ __align__(16) char sm[];
    unsigned smS = (unsigned)__cvta_generic_to_shared(sm);
    unsigned AbS = smS;
    unsigned BbS = smS + STAGES * A_BYTES;

    int tid  = threadIdx.x;
    int warp = tid >> 5, lane = tid & 31;
    int wm = warp >> 2;            // 0..3
    int wn = warp & 3;             // 0..3
    int bm0 = blockIdx.y * BM;
    int bn0 = blockIdx.x * BN;

    float acc[2][NT][4];
    #pragma unroll
    for (int i = 0; i < 2; i++)
        #pragma unroll
        for (int j = 0; j < NT; j++)
            #pragma unroll
            for (int l = 0; l < 4; l++) acc[i][j][l] = 0.0f;

    int g = lane >> 3, lr = lane & 7;
    unsigned a_base = (unsigned)((wm * 32 + (g & 1) * 8 + lr) * A_STRIDE + (g >> 1) * 16);

    auto load_stage = [&](int buf, int k0) {
        // A: 128 rows x 4 chunks of 16B = 512 chunks, 1 per thread
        int row = tid >> 2, c = tid & 3;
        int gr = bm0 + row;
        int cl = (gr < M) ? gr : (M - 1);
        cp_async16s(AbS + buf * A_BYTES + row * A_STRIDE + c * 16,
                    A + (size_t)cl * Kd + k0 + c * 8, gr < M);
        // B: BK rows x BN/8 chunks
        if (tid < BK * (BN / 8)) {
            int br = tid / (BN / 8), bc = tid % (BN / 8);
            cp_async16s(BbS + buf * B_BYTES + br * B_STRIDE + bc * 16,
                        B + (size_t)(k0 + br) * N + bn0 + bc * 8, true);
        }
    };

    int nIter = Kd / BK;
    load_stage(0, 0);
    CP_COMMIT();
    if (1 < nIter) load_stage(1, BK);
    CP_COMMIT();

    for (int it = 0; it < nIter; it++) {
        CP_WAIT(1);
        __syncthreads();

        int pf = it + 2;
        if (pf < nIter) load_stage(pf % STAGES, pf * BK);
        CP_COMMIT();

        int cur = it % STAGES;
        unsigned Ab = AbS + cur * A_BYTES;
        unsigned Bb = BbS + cur * B_BYTES;

        #pragma unroll
        for (int kc = 0; kc < 2; kc++) {
            unsigned a0[4], a1[4], b[NT][2];
            LDMX4(a0[0], a0[1], a0[2], a0[3], Ab + a_base + kc * 32);
            LDMX4(a1[0], a1[1], a1[2], a1[3], Ab + a_base + 16 * A_STRIDE + kc * 32);
            if (BN == 128) {
                unsigned bo = Bb + (kc * 16 + lr) * B_STRIDE + (wn * 32 + g * 8) * 2;
                LDMX4T(b[0][0], b[1][0], b[2][0], b[3][0], bo);
                LDMX4T(b[0][1], b[1][1], b[2][1], b[3][1], bo + 8 * B_STRIDE);
            } else {
                unsigned bo = Bb + (kc * 16 + (g >> 1) * 8 + lr) * B_STRIDE
                            + (wn * 16 + (g & 1) * 8) * 2;
                LDMX4T(b[0][0], b[1][0], b[0][1], b[1][1], bo);
            }
            #pragma unroll
            for (int nt = 0; nt < NT; nt++) {
                MMA_F16(acc[0][nt], a0, b[nt]);
                MMA_F16(acc[1][nt], a1, b[nt]);
            }
        }
    }

    #pragma unroll
    for (int mt = 0; mt < 2; mt++) {
        #pragma unroll
        for (int nt = 0; nt < NT; nt++) {
            int r0 = bm0 + wm * 32 + mt * 16 + (lane >> 2);
            int c0 = bn0 + wn * (BN / 4) + nt * 8 + (lane & 3) * 2;
            float bv0 = bias[c0], bv1 = bias[c0 + 1];
            #pragma unroll
            for (int h = 0; h < 2; h++) {
                int r = r0 + h * 8;
                if (r < M) {
                    float v0 = acc[mt][nt][h * 2 + 0] + bv0;
                    float v1 = acc[mt][nt][h * 2 + 1] + bv1;
                    if (RELU) { v0 = fmaxf(v0, 0.f); v1 = fmaxf(v1, 0.f); }
                    if (OUTF) {
                        C[(size_t)r * N + c0]     = v0;
                        C[(size_t)r * N + c0 + 1] = v1;
                    }
                    if (OUTH) {
                        *(__half2*)&Ch[(size_t)r * N + c0] = __floats2half2_rn(v0, v1);
                    }
                }
            }
        }
    }
}

// ---------------- propagation (fp16 storage, fp32 accumulation, 4-unroll) ----------------
template<bool OUT_HALF>
__global__ __launch_bounds__(256) void prop_kernel(
    const __half* __restrict__ hin, void* __restrict__ hout,
    const __half* __restrict__ h0)
{
    int gt = blockIdx.x * blockDim.x + threadIdx.x;
    int v = gt >> 4;
    if (v >= N_NODES) return;
    int lane = gt & 15;

    int e0 = g_rowptr[v];
    int e1 = g_rowptr[v + 1];
    const uint2* h2 = (const uint2*)hin;

    float4 acc = make_float4(0.f, 0.f, 0.f, 0.f);
    auto accum = [&](float w, uint2 hv) {
        float2 lo = __half22float2(*(const __half2*)&hv.x);
        float2 hi = __half22float2(*(const __half2*)&hv.y);
        acc.x = fmaf(w, lo.x, acc.x); acc.y = fmaf(w, lo.y, acc.y);
        acc.z = fmaf(w, hi.x, acc.z); acc.w = fmaf(w, hi.y, acc.w);
    };

    int e = e0;
    if ((e & 1) && e < e1) {                  // align to 16B pair boundary
        int2 p = __ldg(&g_epack[e]);
        accum(__int_as_float(p.y), h2[(size_t)p.x * 16 + lane]);
        e++;
    }
    for (; e + 4 <= e1; e += 4) {             // 4 independent gathers in flight
        int4 p01 = __ldg((const int4*)&g_epack[e]);
        int4 p23 = __ldg((const int4*)&g_epack[e + 2]);
        uint2 hv0 = h2[(size_t)p01.x * 16 + lane];
        uint2 hv1 = h2[(size_t)p01.z * 16 + lane];
        uint2 hv2 = h2[(size_t)p23.x * 16 + lane];
        uint2 hv3 = h2[(size_t)p23.z * 16 + lane];
        accum(__int_as_float(p01.y), hv0);
        accum(__int_as_float(p01.w), hv1);
        accum(__int_as_float(p23.y), hv2);
        accum(__int_as_float(p23.w), hv3);
    }
    if (e + 2 <= e1) {
        int4 p = __ldg((const int4*)&g_epack[e]);
        uint2 hv0 = h2[(size_t)p.x * 16 + lane];
        uint2 hv1 = h2[(size_t)p.z * 16 + lane];
        accum(__int_as_float(p.y), hv0);
        accum(__int_as_float(p.w), hv1);
        e += 2;
    }
    if (e < e1) {
        int2 p = __ldg(&g_epack[e]);
        accum(__int_as_float(p.y), h2[(size_t)p.x * 16 + lane]);
    }

    accum(g_selfw[v], h2[(size_t)v * 16 + lane]);

    uint2 z2 = ((const uint2*)h0)[(size_t)v * 16 + lane];
    float2 zlo = __half22float2(*(const __half2*)&z2.x);
    float2 zhi = __half22float2(*(const __half2*)&z2.y);
    float4 r;
    r.x = acc.x + 0.1f * zlo.x;
    r.y = acc.y + 0.1f * zlo.y;
    r.z = acc.z + 0.1f * zhi.x;
    r.w = acc.w + 0.1f * zhi.y;

    if (OUT_HALF) {
        uint2 o;
        *(__half2*)&o.x = __floats2half2_rn(r.x, r.y);
        *(__half2*)&o.y = __floats2half2_rn(r.z, r.w);
        ((uint2*)hout)[(size_t)v * 16 + lane] = o;
    } else {
        ((float4*)hout)[(size_t)v * 16 + lane] = r;
    }
}

// ---------------- launch ----------------
extern "C" void kernel_launch(void* const* d_in, const int* in_sizes, int n_in,
                              void* d_out, int out_size)
{
    const float* x  = (const float*)d_in[0];
    const int*   ei = (const int*)d_in[1];     // int32 [2, E]
    const float* w1 = (const float*)d_in[2];
    const float* b1 = (const float*)d_in[3];
    const float* w2 = (const float*)d_in[4];
    const float* b2 = (const float*)d_in[5];
    float*       out = (float*)d_out;

    __half *p_xh, *p_w1h, *p_w2h, *p_hidh, *p_h0h, *p_ha, *p_hb;
    cudaGetSymbolAddress((void**)&p_xh,   g_xh);
    cudaGetSymbolAddress((void**)&p_w1h,  g_w1h);
    cudaGetSymbolAddress((void**)&p_w2h,  g_w2h);
    cudaGetSymbolAddress((void**)&p_hidh, g_hidh);
    cudaGetSymbolAddress((void**)&p_h0h,  g_h0h);
    cudaGetSymbolAddress((void**)&p_ha,   g_ha);
    cudaGetSymbolAddress((void**)&p_hb,   g_hb);

    // dynamic smem sizes: 3 stages * (A 10240 + B BK*B_STRIDE)
    const int SM1 = 3 * (10240 + 32 * (128 * 2 + 16));   // 56832 (>48KB -> attr)
    const int SM2 = 3 * (10240 + 32 * (64 * 2 + 16));    // 44544
    cudaFuncSetAttribute(gemm_kernel<128, true, false, true>,
                         cudaFuncAttributeMaxDynamicSharedMemorySize, SM1);
    cudaFuncSetAttribute(gemm_kernel<64, false, false, true>,
                         cudaFuncAttributeMaxDynamicSharedMemorySize, SM2);

    // launch 0: init + fp16 conversion of x/w1/w2
    init_and_convert<<<(X_ELEMS / 4 + 255) / 256, 256>>>((const float4*)x, w1, w2);
    count_deg<<<(N_EDGES + 255) / 256, 256>>>(ei);
    compute_dinv<<<(N_NODES + 255) / 256, 256>>>();

    // launch index 3 (ncu slot): GEMM1 — fp16 A (x), fp16 B; fp16 out (hidden)
    dim3 g1(HID_CH / 128, (N_NODES + 127) / 128);
    gemm_kernel<128, true, false, true><<<g1, 512, SM1>>>(
        p_xh, p_w1h, b1, nullptr, p_hidh, N_NODES, HID_CH, IN_CH);

    scan_p1<<<NB_SCAN, 256>>>();
    scan_p2<<<1, 512>>>();
    scan_p3<<<NB_SCAN, 256>>>();
    fill_csr<<<(N_EDGES + 255) / 256, 256>>>(ei);

    // GEMM2 — fp16 A (hidden), fp16 B; writes fp16 h0
    dim3 g2(1, (N_NODES + 127) / 128);
    gemm_kernel<64, false, false, true><<<g2, 512, SM2>>>(
        p_hidh, p_w2h, b2, nullptr, p_h0h, N_NODES, OUT_CH, HID_CH);

    // APPNP: steps 0..8 fp16 ping-pong, step 9 writes fp32 to d_out
    int grid = (N_NODES * 16 + 255) / 256;
    const __half* cur = p_h0h;
    for (int s = 0; s < K_STEPS - 1; s++) {
        __half* o = (s & 1) ? p_hb : p_ha;
        prop_kernel<true><<<grid, 256>>>(cur, o, p_h0h);
        cur = o;
    }
    prop_kernel<false><<<grid, 256>>>(cur, out, p_h0h);
}

// round 17
// speedup vs baseline: 1.1149x; 1.0550x over previous
#include <cuda_runtime.h>
#include <cuda_fp16.h>
#include <cstdint>

#define N_NODES 100000
#define N_EDGES 1600000
#define IN_CH   512
#define HID_CH  256
#define OUT_CH  64
#define K_STEPS 10
#define NB_SCAN ((N_NODES + 255) / 256)   // 391
#define W1_ELEMS (IN_CH * HID_CH)
#define W2_ELEMS (HID_CH * OUT_CH)

// ---------------- scratch (static __device__, no allocation) ----------------
__device__ int   g_deg[N_NODES];
__device__ int   g_cursor[N_NODES];
__device__ float g_dinv[N_NODES];
__device__ float g_selfw[N_NODES];
__device__ int   g_rowptr[N_NODES + 1];
__device__ int   g_part[NB_SCAN];
__device__ __align__(16) int2   g_epack[N_EDGES];
__device__ __align__(16) __half g_w1h[W1_ELEMS];   // w1 [K][N] fp16
__device__ __align__(16) __half g_w2h[W2_ELEMS];   // w2 [K][N] fp16
__device__ __align__(16) __half g_hidh[(size_t)N_NODES * HID_CH];  // fp16 hidden
__device__ __align__(16) __half g_h0h [(size_t)N_NODES * OUT_CH];  // fp16 h0
__device__ __align__(16) __half g_ha  [(size_t)N_NODES * OUT_CH];
__device__ __align__(16) __half g_hb  [(size_t)N_NODES * OUT_CH];

// ---------------- preprocessing ----------------
__global__ void init_and_convert(const float* __restrict__ w1,
                                 const float* __restrict__ w2)
{
    int i = blockIdx.x * blockDim.x + threadIdx.x;
    if (i < N_NODES) { g_deg[i] = 1; g_cursor[i] = 0; }
    if (i < W1_ELEMS) g_w1h[i] = __float2half_rn(w1[i]);
    if (i < W2_ELEMS) g_w2h[i] = __float2half_rn(w2[i]);
}

__global__ void count_deg(const int* __restrict__ ei)
{
    int e = blockIdx.x * blockDim.x + threadIdx.x;
    if (e < N_EDGES) {
        int d = ei[N_EDGES + e];
        if ((unsigned)d < N_NODES) atomicAdd(&g_deg[d], 1);
    }
}

__global__ void compute_dinv()
{
    int i = blockIdx.x * blockDim.x + threadIdx.x;
    if (i < N_NODES) {
        float dv = rsqrtf((float)g_deg[i]);
        g_dinv[i]  = dv;
        g_selfw[i] = 0.9f * dv * dv;
    }
}

__global__ void scan_p1()
{
    int b = blockIdx.x, t = threadIdx.x;
    int i = b * 256 + t;
    int v = (i < N_NODES) ? (g_deg[i] - 1) : 0;
    int lane = t & 31, w = t >> 5;
    int x = v;
    #pragma unroll
    for (int o = 1; o < 32; o <<= 1) {
        int y = __shfl_up_sync(0xffffffffu, x, o);
        if (lane >= o) x += y;
    }
    __shared__ int wsum[8];
    if (lane == 31) wsum[w] = x;
    __syncthreads();
    if (t < 8) {
        int s = wsum[t];
        #pragma unroll
        for (int o = 1; o < 8; o <<= 1) {
            int y = __shfl_up_sync(0xffu, s, o);
            if (t >= o) s += y;
        }
        wsum[t] = s;
    }
    __syncthreads();
    int base = (w > 0) ? wsum[w - 1] : 0;
    if (i < N_NODES) g_rowptr[i] = base + x - v;
    if (t == 255) g_part[b] = wsum[7];
}

__global__ void scan_p2()
{
    __shared__ int s[512];
    int t = threadIdx.x;
    int v = (t < NB_SCAN) ? g_part[t] : 0;
    s[t] = v;
    __syncthreads();
    for (int o = 1; o < 512; o <<= 1) {
        int y = (t >= o) ? s[t - o] : 0;
        __syncthreads();
        s[t] += y;
        __syncthreads();
    }
    if (t < NB_SCAN) g_part[t] = s[t] - v;
    if (t == NB_SCAN - 1) g_rowptr[N_NODES] = s[t];
}

__global__ void scan_p3()
{
    int b = blockIdx.x, t = threadIdx.x;
    int i = b * 256 + t;
    if (i < N_NODES) g_rowptr[i] += g_part[b];
}

__global__ void fill_csr(const int* __restrict__ ei)
{
    int idx = blockIdx.x * blockDim.x + threadIdx.x;
    if (idx < N_EDGES) {
        int s = ei[idx];
        int d = ei[N_EDGES + idx];
        if ((unsigned)s >= N_NODES || (unsigned)d >= N_NODES) return;
        int pos = g_rowptr[d] + atomicAdd(&g_cursor[d], 1);
        int2 p;
        p.x = s;
        p.y = __float_as_int(0.9f * g_dinv[s] * g_dinv[d]);
        g_epack[pos] = p;
    }
}

// ---------------- fp16 tensor-core GEMM: cp.async + ldmatrix, BK=32 ----------------
__device__ __forceinline__ void cp_async16s(unsigned smem_addr, const void* gmem_src)
{
    asm volatile("cp.async.cg.shared.global [%0], [%1], 16;\n"
                 :: "r"(smem_addr), "l"(gmem_src));
}
#define CP_COMMIT() asm volatile("cp.async.commit_group;\n" ::: "memory")
#define CP_WAIT(n)  asm volatile("cp.async.wait_group %0;\n" :: "n"(n) : "memory")

#define MMA_F16(d, a, b)                                                          \
    asm volatile("mma.sync.aligned.m16n8k16.row.col.f32.f16.f16.f32 "             \
                 "{%0,%1,%2,%3},{%4,%5,%6,%7},{%8,%9},{%0,%1,%2,%3};\n"           \
                 : "+f"(d[0]), "+f"(d[1]), "+f"(d[2]), "+f"(d[3])                 \
                 : "r"(a[0]), "r"(a[1]), "r"(a[2]), "r"(a[3]),                    \
                   "r"(b[0]), "r"(b[1]))

#define LDMX4(r0, r1, r2, r3, addr)                                               \
    asm volatile("ldmatrix.sync.aligned.m8n8.x4.shared.b16 {%0,%1,%2,%3}, [%4];"  \
                 : "=r"(r0), "=r"(r1), "=r"(r2), "=r"(r3) : "r"(addr))

#define LDMX4T(r0, r1, r2, r3, addr)                                                   \
    asm volatile("ldmatrix.sync.aligned.m8n8.x4.trans.shared.b16 {%0,%1,%2,%3}, [%4];" \
                 : "=r"(r0), "=r"(r1), "=r"(r2), "=r"(r3) : "r"(addr))

__device__ __forceinline__ unsigned packh2(float lo, float hi)
{
    __half2 h = __floats2half2_rn(lo, hi);
    return *(unsigned*)&h;
}

// BM=128, BK=32, 512 threads (16 warps as 4m x 4n -> warp tile 32 x BN/4).
// 3-stage cp.async pipeline, 2 CTAs/SM, fp16 m16n8k16 MMA, fp32 acc.
// AF32: A fp32 in gmem, staged via cp.async into fp32 smem (3 stages), then
//       converted smem->smem (fp16, single buffer) after the wait. Latency stays
//       hidden by cp.async; conversion costs 2 LDS.128 + 4 packs + 1 STS.128.
// else: A fp16 in gmem, straight 3-stage cp.async.
// B fp16 [K][N] via 3-stage cp.async. Fragments via ldmatrix.
template<int BN, bool AF32, bool RELU, bool OUTF, bool OUTH>
__global__ __launch_bounds__(512, 2) void gemm_kernel(
    const void* __restrict__ Av, const __half* __restrict__ B,
    const float* __restrict__ bias, float* __restrict__ C,
    __half* __restrict__ Ch, int M, int N, int Kd)
{
    const int BM = 128, BK = 32, STAGES = 3;
    const int NT = BN / 32;
    const int A32_STRIDE = 144;                   // 32 floats (128B) + 16B pad
    const int A32_BYTES  = BM * A32_STRIDE;       // 18432
    const int A16_STRIDE = 80;                    // 32 halves (64B) + 16B pad
    const int A16_BYTES  = BM * A16_STRIDE;       // 10240
    const int B_STRIDE   = BN * 2 + 16;
    const int B_BYTES    = BK * B_STRIDE;

    extern __shared__ __align__(16) char sm[];
    unsigned smS = (unsigned)__cvta_generic_to_shared(sm);
    // layout: AF32: [A32 x3 | A16 x1 | B x3]   else: [A16 x3 | B x3]
    unsigned A32S = smS;
    unsigned A16S = AF32 ? (smS + STAGES * A32_BYTES) : smS;
    unsigned BbS  = AF32 ? (A16S + A16_BYTES) : (smS + STAGES * A16_BYTES);

    int tid  = threadIdx.x;
    int warp = tid >> 5, lane = tid & 31;
    int wm = warp >> 2;
    int wn = warp & 3;
    int bm0 = blockIdx.y * BM;
    int bn0 = blockIdx.x * BN;

    float acc[2][NT][4];
    #pragma unroll
    for (int i = 0; i < 2; i++)
        #pragma unroll
        for (int j = 0; j < NT; j++)
            #pragma unroll
            for (int l = 0; l < 4; l++) acc[i][j][l] = 0.0f;

    int g = lane >> 3, lr = lane & 7;
    unsigned a_base = (unsigned)((wm * 32 + (g & 1) * 8 + lr) * A16_STRIDE + (g >> 1) * 16);

    // staging coords (A): 128 rows x 4 chunks; fp16: 16B/chunk; fp32: 32B/chunk
    int arow = tid >> 2, ac = tid & 3;
    int agr = bm0 + arow;
    int acl = (agr < M) ? agr : (M - 1);           // clamp; masked at epilogue

    auto load_stage = [&](int buf, int k0) {
        if (AF32) {
            unsigned dst = A32S + buf * A32_BYTES + arow * A32_STRIDE + ac * 32;
            const float* src = (const float*)Av + (size_t)acl * Kd + k0 + ac * 8;
            cp_async16s(dst, src);
            cp_async16s(dst + 16, src + 4);
        } else {
            cp_async16s(A16S + buf * A16_BYTES + arow * A16_STRIDE + ac * 16,
                        (const __half*)Av + (size_t)acl * Kd + k0 + ac * 8);
        }
        if (tid < BK * (BN / 8)) {
            int br = tid / (BN / 8), bc = tid % (BN / 8);
            cp_async16s(BbS + buf * B_BYTES + br * B_STRIDE + bc * 16,
                        B + (size_t)(k0 + br) * N + bn0 + bc * 8);
        }
    };

    int nIter = Kd / BK;
    load_stage(0, 0);
    CP_COMMIT();
    if (1 < nIter) load_stage(1, BK);
    CP_COMMIT();

    for (int it = 0; it < nIter; it++) {
        CP_WAIT(1);
        __syncthreads();

        int pf = it + 2;
        if (pf < nIter) load_stage(pf % STAGES, pf * BK);
        CP_COMMIT();

        int cur = it % STAGES;
        unsigned Ab;
        if (AF32) {
            // convert this stage's fp32 A tile into the single fp16 buffer
            const float4* s32 = (const float4*)(sm + (size_t)cur * A32_BYTES
                                                + arow * A32_STRIDE + ac * 32);
            float4 v0 = s32[0];
            float4 v1 = s32[1];
            unsigned o0 = packh2(v0.x, v0.y), o1 = packh2(v0.z, v0.w);
            unsigned o2 = packh2(v1.x, v1.y), o3 = packh2(v1.z, v1.w);
            asm volatile("st.shared.v4.b32 [%0], {%1,%2,%3,%4};"
                         :: "r"(A16S + arow * A16_STRIDE + ac * 16),
                            "r"(o0), "r"(o1), "r"(o2), "r"(o3));
            __syncthreads();
            Ab = A16S;
        } else {
            Ab = A16S + cur * A16_BYTES;
        }
        unsigned Bb = BbS + cur * B_BYTES;

        #pragma unroll
        for (int kc = 0; kc < 2; kc++) {
            unsigned a0[4], a1[4], b[NT][2];
            LDMX4(a0[0], a0[1], a0[2], a0[3], Ab + a_base + kc * 32);
            LDMX4(a1[0], a1[1], a1[2], a1[3], Ab + a_base + 16 * A16_STRIDE + kc * 32);
            if (BN == 128) {
                unsigned bo = Bb + (kc * 16 + lr) * B_STRIDE + (wn * 32 + g * 8) * 2;
                LDMX4T(b[0][0], b[1][0], b[2][0], b[3][0], bo);
                LDMX4T(b[0][1], b[1][1], b[2][1], b[3][1], bo + 8 * B_STRIDE);
            } else {
                unsigned bo = Bb + (kc * 16 + (g >> 1) * 8 + lr) * B_STRIDE
                            + (wn * 16 + (g & 1) * 8) * 2;
                LDMX4T(b[0][0], b[1][0], b[0][1], b[1][1], bo);
            }
            #pragma unroll
            for (int nt = 0; nt < NT; nt++) {
                MMA_F16(acc[0][nt], a0, b[nt]);
                MMA_F16(acc[1][nt], a1, b[nt]);
            }
        }
    }

    #pragma unroll
    for (int mt = 0; mt < 2; mt++) {
        #pragma unroll
        for (int nt = 0; nt < NT; nt++) {
            int r0 = bm0 + wm * 32 + mt * 16 + (lane >> 2);
            int c0 = bn0 + wn * (BN / 4) + nt * 8 + (lane & 3) * 2;
            float bv0 = bias[c0], bv1 = bias[c0 + 1];
            #pragma unroll
            for (int h = 0; h < 2; h++) {
                int r = r0 + h * 8;
                if (r < M) {
                    float v0 = acc[mt][nt][h * 2 + 0] + bv0;
                    float v1 = acc[mt][nt][h * 2 + 1] + bv1;
                    if (RELU) { v0 = fmaxf(v0, 0.f); v1 = fmaxf(v1, 0.f); }
                    if (OUTF) {
                        C[(size_t)r * N + c0]     = v0;
                        C[(size_t)r * N + c0 + 1] = v1;
                    }
                    if (OUTH) {
                        *(__half2*)&Ch[(size_t)r * N + c0] = __floats2half2_rn(v0, v1);
                    }
                }
            }
        }
    }
}

// ---------------- propagation (fp16, fp32 acc, 8 lanes x 16B per node) ----------------
template<bool OUT_HALF>
__global__ __launch_bounds__(256) void prop_kernel(
    const __half* __restrict__ hin, void* __restrict__ hout,
    const __half* __restrict__ h0)
{
    int gt = blockIdx.x * blockDim.x + threadIdx.x;
    int v = gt >> 3;
    if (v >= N_NODES) return;
    int lane = gt & 7;

    int e0 = g_rowptr[v];
    int e1 = g_rowptr[v + 1];
    const uint4* h4 = (const uint4*)hin;   // 8 uint4 per 64-ch node row

    float a0 = 0.f, a1 = 0.f, a2 = 0.f, a3 = 0.f;
    float a4 = 0.f, a5 = 0.f, a6 = 0.f, a7 = 0.f;
    auto accum = [&](float w, uint4 hv) {
        float2 f0 = __half22float2(*(const __half2*)&hv.x);
        float2 f1 = __half22float2(*(const __half2*)&hv.y);
        float2 f2 = __half22float2(*(const __half2*)&hv.z);
        float2 f3 = __half22float2(*(const __half2*)&hv.w);
        a0 = fmaf(w, f0.x, a0); a1 = fmaf(w, f0.y, a1);
        a2 = fmaf(w, f1.x, a2); a3 = fmaf(w, f1.y, a3);
        a4 = fmaf(w, f2.x, a4); a5 = fmaf(w, f2.y, a5);
        a6 = fmaf(w, f3.x, a6); a7 = fmaf(w, f3.y, a7);
    };

    int e = e0;
    if ((e & 1) && e < e1) {                  // align to 16B pair boundary
        int2 p = __ldg(&g_epack[e]);
        accum(__int_as_float(p.y), h4[(size_t)p.x * 8 + lane]);
        e++;
    }
    for (; e + 4 <= e1; e += 4) {             // 4 independent gathers in flight
        int4 p01 = __ldg((const int4*)&g_epack[e]);
        int4 p23 = __ldg((const int4*)&g_epack[e + 2]);
        uint4 hv0 = h4[(size_t)p01.x * 8 + lane];
        uint4 hv1 = h4[(size_t)p01.z * 8 + lane];
        uint4 hv2 = h4[(size_t)p23.x * 8 + lane];
        uint4 hv3 = h4[(size_t)p23.z * 8 + lane];
        accum(__int_as_float(p01.y), hv0);
        accum(__int_as_float(p01.w), hv1);
        accum(__int_as_float(p23.y), hv2);
        accum(__int_as_float(p23.w), hv3);
    }
    if (e + 2 <= e1) {
        int4 p = __ldg((const int4*)&g_epack[e]);
        uint4 hv0 = h4[(size_t)p.x * 8 + lane];
        uint4 hv1 = h4[(size_t)p.z * 8 + lane];
        accum(__int_as_float(p.y), hv0);
        accum(__int_as_float(p.w), hv1);
        e += 2;
    }
    if (e < e1) {
        int2 p = __ldg(&g_epack[e]);
        accum(__int_as_float(p.y), h4[(size_t)p.x * 8 + lane]);
    }

    accum(g_selfw[v], h4[(size_t)v * 8 + lane]);

    // alpha * h0 (fp16 storage)
    uint4 z = ((const uint4*)h0)[(size_t)v * 8 + lane];
    float2 z0 = __half22float2(*(const __half2*)&z.x);
    float2 z1 = __half22float2(*(const __half2*)&z.y);
    float2 z2 = __half22float2(*(const __half2*)&z.z);
    float2 z3 = __half22float2(*(const __half2*)&z.w);
    float r0 = a0 + 0.1f * z0.x, r1 = a1 + 0.1f * z0.y;
    float r2 = a2 + 0.1f * z1.x, r3 = a3 + 0.1f * z1.y;
    float r4 = a4 + 0.1f * z2.x, r5 = a5 + 0.1f * z2.y;
    float r6 = a6 + 0.1f * z3.x, r7 = a7 + 0.1f * z3.y;

    if (OUT_HALF) {
        uint4 o;
        *(__half2*)&o.x = __floats2half2_rn(r0, r1);
        *(__half2*)&o.y = __floats2half2_rn(r2, r3);
        *(__half2*)&o.z = __floats2half2_rn(r4, r5);
        *(__half2*)&o.w = __floats2half2_rn(r6, r7);
        ((uint4*)hout)[(size_t)v * 8 + lane] = o;
    } else {
        float4* o = (float4*)hout + (size_t)v * 16 + lane * 2;
        o[0] = make_float4(r0, r1, r2, r3);
        o[1] = make_float4(r4, r5, r6, r7);
    }
}

// ---------------- launch ----------------
extern "C" void kernel_launch(void* const* d_in, const int* in_sizes, int n_in,
                              void* d_out, int out_size)
{
    const float* x  = (const float*)d_in[0];
    const int*   ei = (const int*)d_in[1];     // int32 [2, E]
    const float* w1 = (const float*)d_in[2];
    const float* b1 = (const float*)d_in[3];
    const float* w2 = (const float*)d_in[4];
    const float* b2 = (const float*)d_in[5];
    float*       out = (float*)d_out;

    __half *p_w1h, *p_w2h, *p_hidh, *p_h0h, *p_ha, *p_hb;
    cudaGetSymbolAddress((void**)&p_w1h,  g_w1h);
    cudaGetSymbolAddress((void**)&p_w2h,  g_w2h);
    cudaGetSymbolAddress((void**)&p_hidh, g_hidh);
    cudaGetSymbolAddress((void**)&p_h0h,  g_h0h);
    cudaGetSymbolAddress((void**)&p_ha,   g_ha);
    cudaGetSymbolAddress((void**)&p_hb,   g_hb);

    // dynamic smem: GEMM1 (AF32): 3*18432 + 10240 + 3*(32*272) = 91648
    //               GEMM2 (fp16): 3*10240 + 3*(32*144)          = 44544
    const int SM1 = 3 * 18432 + 10240 + 3 * (32 * (128 * 2 + 16));
    const int SM2 = 3 * 10240 + 3 * (32 * (64 * 2 + 16));
    cudaFuncSetAttribute(gemm_kernel<128, true, true, false, true>,
                         cudaFuncAttributeMaxDynamicSharedMemorySize, SM1);
    cudaFuncSetAttribute(gemm_kernel<64, false, false, false, true>,
                         cudaFuncAttributeMaxDynamicSharedMemorySize, SM2);

    // launches 0-2: preprocessing (weights fp16 fused into 0; x stays fp32)
    init_and_convert<<<(W1_ELEMS + 255) / 256, 256>>>(w1, w2);
    count_deg<<<(N_EDGES + 255) / 256, 256>>>(ei);
    compute_dinv<<<(N_NODES + 255) / 256, 256>>>();

    // launch index 3 (ncu slot): GEMM1 — fp32 A (x) converted in-pipeline, fp16 B
    dim3 g1(HID_CH / 128, (N_NODES + 127) / 128);
    gemm_kernel<128, true, true, false, true><<<g1, 512, SM1>>>(
        x, p_w1h, b1, nullptr, p_hidh, N_NODES, HID_CH, IN_CH);

    scan_p1<<<NB_SCAN, 256>>>();
    scan_p2<<<1, 512>>>();
    scan_p3<<<NB_SCAN, 256>>>();
    fill_csr<<<(N_EDGES + 255) / 256, 256>>>(ei);

    // GEMM2 — fp16 A (hidden), fp16 B; writes fp16 h0
    dim3 g2(1, (N_NODES + 127) / 128);
    gemm_kernel<64, false, false, false, true><<<g2, 512, SM2>>>(
        p_hidh, p_w2h, b2, nullptr, p_h0h, N_NODES, OUT_CH, HID_CH);

    // APPNP: steps 0..8 fp16 ping-pong, step 9 writes fp32 to d_out
    int grid = (N_NODES * 8 + 255) / 256;
    const __half* cur = p_h0h;
    for (int s = 0; s < K_STEPS - 1; s++) {
        __half* o = (s & 1) ? p_hb : p_ha;
        prop_kernel<true><<<grid, 256>>>(cur, o, p_h0h);
        cur = o;
    }
    prop_kernel<false><<<grid, 256>>>(cur, out, p_h0h);
}